// round 1
// baseline (speedup 1.0000x reference)
#include <cuda_runtime.h>
#include <cuda_bf16.h>

// SemiSparseCRFLoss on GB300:
//   loss = (1/(4*B*H*W)) * sum_b sel[b] * sum_{shifts} sum_{h,w}
//            [ (exp(-d2/(2*sigma^2))*w_xy - eps) * v ] * [ (y - y_sh)^2 * v ]
// shifts = (0,1),(1,0),(1,1),(1,-1); only y_pr channel 1 is used; y_gt unused.

#define HH 512
#define WW 512
#define BB 16

__device__ __forceinline__ float shift_term(float a0, float a1, float a2,
                                            float b0, float b1, float b2,
                                            float ya, float yb,
                                            float wxy) {
    const float INV2S2 = 22.222222222222221f;   // 1/(2*0.15^2)
    float dx0 = a0 - b0;
    float dx1 = a1 - b1;
    float dx2 = a2 - b2;
    float d2 = dx0 * dx0 + dx1 * dx1 + dx2 * dx2;
    float m = __expf(-d2 * INV2S2) * wxy - 0.01f;   // SUB_EPS
    float dy = ya - yb;
    return m * dy * dy;
}

__global__ void __launch_bounds__(256, 8)
crf_loss_kernel(const float* __restrict__ ypr,
                const float* __restrict__ img,
                const int* __restrict__ icls,
                float* __restrict__ out) {
    const int b = blockIdx.y;
    if (icls[b] == 0) return;               // sel == 0: whole image contributes nothing

    const int tid = threadIdx.x;
    const int row = (blockIdx.x << 1) + (tid >> 7);   // 2 rows per block
    const int w0  = (tid & 127) << 2;                 // 4 pixels per thread

    const float* y  = ypr + ((size_t)b * 2 + 1) * (HH * WW) + (size_t)row * WW;
    const float* i0 = img + ((size_t)b * 3 + 0) * (HH * WW) + (size_t)row * WW;
    const float* i1 = i0 + HH * WW;
    const float* i2 = i1 + HH * WW;

    const float WXY1 = 0.60653065971263342f;  // exp(-0.5)
    const float WXY2 = 0.36787944117144233f;  // exp(-1.0)

    // center row: values at w0 .. w0+4  (index k -> w0+k)
    float yc[5], c0[5], c1[5], c2[5];
    {
        float4 t;
        t = *(const float4*)(y  + w0); yc[0]=t.x; yc[1]=t.y; yc[2]=t.z; yc[3]=t.w;
        t = *(const float4*)(i0 + w0); c0[0]=t.x; c0[1]=t.y; c0[2]=t.z; c0[3]=t.w;
        t = *(const float4*)(i1 + w0); c1[0]=t.x; c1[1]=t.y; c1[2]=t.z; c1[3]=t.w;
        t = *(const float4*)(i2 + w0); c2[0]=t.x; c2[1]=t.y; c2[2]=t.z; c2[3]=t.w;
        const bool haveR = (w0 + 4 < WW);
        yc[4] = haveR ? y [w0 + 4] : 0.0f;
        c0[4] = haveR ? i0[w0 + 4] : 0.0f;
        c1[4] = haveR ? i1[w0 + 4] : 0.0f;
        c2[4] = haveR ? i2[w0 + 4] : 0.0f;
    }

    // down row (row+1): values at w0-1 .. w0+4  (index j -> w0-1+j)
    const bool haveDown = (row + 1 < HH);
    float yd[6] = {0,0,0,0,0,0};
    float d0[6] = {0,0,0,0,0,0};
    float d1[6] = {0,0,0,0,0,0};
    float d2a[6] = {0,0,0,0,0,0};
    if (haveDown) {
        const float* yD  = y  + WW;
        const float* i0D = i0 + WW;
        const float* i1D = i1 + WW;
        const float* i2D = i2 + WW;
        float4 t;
        t = *(const float4*)(yD  + w0); yd [1]=t.x; yd [2]=t.y; yd [3]=t.z; yd [4]=t.w;
        t = *(const float4*)(i0D + w0); d0 [1]=t.x; d0 [2]=t.y; d0 [3]=t.z; d0 [4]=t.w;
        t = *(const float4*)(i1D + w0); d1 [1]=t.x; d1 [2]=t.y; d1 [3]=t.z; d1 [4]=t.w;
        t = *(const float4*)(i2D + w0); d2a[1]=t.x; d2a[2]=t.y; d2a[3]=t.z; d2a[4]=t.w;
        if (w0 > 0) {
            yd [0] = yD [w0 - 1];
            d0 [0] = i0D[w0 - 1];
            d1 [0] = i1D[w0 - 1];
            d2a[0] = i2D[w0 - 1];
        }
        if (w0 + 4 < WW) {
            yd [5] = yD [w0 + 4];
            d0 [5] = i0D[w0 + 4];
            d1 [5] = i1D[w0 + 4];
            d2a[5] = i2D[w0 + 4];
        }
    }

    float acc = 0.0f;
#pragma unroll
    for (int k = 0; k < 4; k++) {
        const int w = w0 + k;
        const float ya = yc[k];
        const float a0 = c0[k], a1 = c1[k], a2 = c2[k];
        const bool rightOK = (w + 1 < WW);
        const bool leftOK  = (w - 1 >= 0);

        // shift (0, 1): neighbor (row, w+1)
        if (rightOK)
            acc += shift_term(a0, a1, a2, c0[k+1], c1[k+1], c2[k+1], ya, yc[k+1], WXY1);

        if (haveDown) {
            // shift (1, 0): neighbor (row+1, w) -> down index k+1
            acc += shift_term(a0, a1, a2, d0[k+1], d1[k+1], d2a[k+1], ya, yd[k+1], WXY1);
            // shift (1, 1): neighbor (row+1, w+1) -> down index k+2
            if (rightOK)
                acc += shift_term(a0, a1, a2, d0[k+2], d1[k+2], d2a[k+2], ya, yd[k+2], WXY2);
            // shift (1, -1): neighbor (row+1, w-1) -> down index k
            if (leftOK)
                acc += shift_term(a0, a1, a2, d0[k], d1[k], d2a[k], ya, yd[k], WXY2);
        }
    }

    // block reduction
#pragma unroll
    for (int o = 16; o > 0; o >>= 1)
        acc += __shfl_down_sync(0xffffffffu, acc, o);

    __shared__ float sm[8];
    const int wid  = tid >> 5;
    const int lane = tid & 31;
    if (lane == 0) sm[wid] = acc;
    __syncthreads();
    if (wid == 0) {
        float v = (lane < 8) ? sm[lane] : 0.0f;
#pragma unroll
        for (int o = 4; o > 0; o >>= 1)
            v += __shfl_down_sync(0xffffffffu, v, o);
        if (lane == 0) {
            const float SCALE = 1.0f / (float)((size_t)HH * WW * BB * 4);  // WEIGHT=1
            atomicAdd(out, v * SCALE);
        }
    }
}

__global__ void zero_out_kernel(float* out) {
    if (threadIdx.x == 0) out[0] = 0.0f;
}

extern "C" void kernel_launch(void* const* d_in, const int* in_sizes, int n_in,
                              void* d_out, int out_size) {
    const float* ypr  = (const float*)d_in[0];   // y_pr  (16,2,512,512)
    // d_in[1] = y_gt (unused by the reference)
    const float* img  = (const float*)d_in[2];   // image (16,3,512,512)
    const int*   icls = (const int*)d_in[3];     // image_class (16,)
    float* out = (float*)d_out;

    zero_out_kernel<<<1, 32>>>(out);
    dim3 grid(HH / 2, BB);   // 256 tiles of 2 rows, per batch
    crf_loss_kernel<<<grid, 256>>>(ypr, img, icls, out);
}

// round 2
// speedup vs baseline: 1.5415x; 1.5415x over previous
#include <cuda_runtime.h>
#include <cuda_bf16.h>

// SemiSparseCRFLoss:
//   loss = (1/(4*B*H*W)) * sum_b sel[b] * sum_{shifts} sum_{h,w}
//          [(exp(-d2/(2*sigma^2))*w_xy - eps)*v] * [(y - y_sh)^2 * v]
// shifts (0,1),(1,0),(1,1),(1,-1); only y_pr channel 1 used; y_gt unused.

#define HH 512
#define WW 512
#define BB 16
#define RPB 4   // rows per block (strip height)

__device__ __forceinline__ float shift_term(float a0, float a1, float a2,
                                            float b0, float b1, float b2,
                                            float ya, float yb, float wxy) {
    const float INV2S2 = 22.222222222222221f;   // 1/(2*0.15^2)
    float dx0 = a0 - b0, dx1 = a1 - b1, dx2 = a2 - b2;
    float d2 = dx0 * dx0 + dx1 * dx1 + dx2 * dx2;
    float m = __expf(-d2 * INV2S2) * wxy - 0.01f;  // SUB_EPS
    float dy = ya - yb;
    return m * dy * dy;
}

__global__ void __launch_bounds__(128, 8)
crf_loss_kernel(const float* __restrict__ ypr,
                const float* __restrict__ img,
                const int* __restrict__ icls,
                float* __restrict__ out) {
    const int b = blockIdx.y;
    if (icls[b] == 0) return;   // sel == 0 -> whole batch contributes nothing

    const int tid  = threadIdx.x;
    const int lane = tid & 31;
    const int w0   = tid << 2;                 // 4 px per thread, 128 threads = full row
    const int r0   = blockIdx.x * RPB;

    const float* Y  = ypr + ((size_t)(2 * b + 1)) * (HH * WW);
    const float* I0 = img + ((size_t)(3 * b))     * (HH * WW);
    const float* I1 = I0 + HH * WW;
    const float* I2 = I1 + HH * WW;

    const unsigned FULL = 0xffffffffu;
    const bool lastLane  = (lane == 31);
    const bool firstLane = (lane == 0);
    const bool hasR = (w0 + 4 < WW);   // false only for tid 127
    const bool hasL = (w0 > 0);        // false only for tid 0

    const float WXY1 = 0.60653065971263342f;  // exp(-0.5)
    const float WXY2 = 0.36787944117144233f;  // exp(-1.0)

    // ---- current row registers (row r) + right halo (value at w0+4) ----
    float cy[4], ca[4], cb[4], cc[4];
    float cyR, caR, cbR, ccR;
    {
        const int off = r0 * WW + w0;
        float4 t;
        t = *(const float4*)(Y  + off); cy[0]=t.x; cy[1]=t.y; cy[2]=t.z; cy[3]=t.w;
        t = *(const float4*)(I0 + off); ca[0]=t.x; ca[1]=t.y; ca[2]=t.z; ca[3]=t.w;
        t = *(const float4*)(I1 + off); cb[0]=t.x; cb[1]=t.y; cb[2]=t.z; cb[3]=t.w;
        t = *(const float4*)(I2 + off); cc[0]=t.x; cc[1]=t.y; cc[2]=t.z; cc[3]=t.w;
        cyR = __shfl_down_sync(FULL, cy[0], 1);
        caR = __shfl_down_sync(FULL, ca[0], 1);
        cbR = __shfl_down_sync(FULL, cb[0], 1);
        ccR = __shfl_down_sync(FULL, cc[0], 1);
        if (lastLane) {   // cross-warp boundary: one scalar load per array
            cyR = hasR ? Y [off + 4] : 0.0f;
            caR = hasR ? I0[off + 4] : 0.0f;
            cbR = hasR ? I1[off + 4] : 0.0f;
            ccR = hasR ? I2[off + 4] : 0.0f;
        }
    }

    float acc = 0.0f;

#pragma unroll
    for (int rr = 0; rr < RPB; rr++) {
        const int r = r0 + rr;
        const bool haveDown = (r + 1 < HH);   // uniform across block

        // ---- load next row (r+1) + halos ----
        float ny[4], na[4], nb[4], nc[4];
        float nyR = 0.f, naR = 0.f, nbR = 0.f, ncR = 0.f;
        float nyL = 0.f, naL = 0.f, nbL = 0.f, ncL = 0.f;
        if (haveDown) {
            const int off = (r + 1) * WW + w0;
            float4 t;
            t = *(const float4*)(Y  + off); ny[0]=t.x; ny[1]=t.y; ny[2]=t.z; ny[3]=t.w;
            t = *(const float4*)(I0 + off); na[0]=t.x; na[1]=t.y; na[2]=t.z; na[3]=t.w;
            t = *(const float4*)(I1 + off); nb[0]=t.x; nb[1]=t.y; nb[2]=t.z; nb[3]=t.w;
            t = *(const float4*)(I2 + off); nc[0]=t.x; nc[1]=t.y; nc[2]=t.z; nc[3]=t.w;

            nyR = __shfl_down_sync(FULL, ny[0], 1);
            naR = __shfl_down_sync(FULL, na[0], 1);
            nbR = __shfl_down_sync(FULL, nb[0], 1);
            ncR = __shfl_down_sync(FULL, nc[0], 1);
            if (lastLane) {
                nyR = hasR ? Y [off + 4] : 0.0f;
                naR = hasR ? I0[off + 4] : 0.0f;
                nbR = hasR ? I1[off + 4] : 0.0f;
                ncR = hasR ? I2[off + 4] : 0.0f;
            }
            nyL = __shfl_up_sync(FULL, ny[3], 1);
            naL = __shfl_up_sync(FULL, na[3], 1);
            nbL = __shfl_up_sync(FULL, nb[3], 1);
            ncL = __shfl_up_sync(FULL, nc[3], 1);
            if (firstLane) {
                nyL = hasL ? Y [off - 1] : 0.0f;
                naL = hasL ? I0[off - 1] : 0.0f;
                nbL = hasL ? I1[off - 1] : 0.0f;
                ncL = hasL ? I2[off - 1] : 0.0f;
            }
        } else {
#pragma unroll
            for (int k = 0; k < 4; k++) { ny[k]=0.f; na[k]=0.f; nb[k]=0.f; nc[k]=0.f; }
        }

        // ---- horizontal shift (0,1) on current row ----
#pragma unroll
        for (int k = 0; k < 3; k++)
            acc += shift_term(ca[k], cb[k], cc[k],
                              ca[k+1], cb[k+1], cc[k+1],
                              cy[k], cy[k+1], WXY1);
        if (hasR)
            acc += shift_term(ca[3], cb[3], cc[3], caR, cbR, ccR,
                              cy[3], cyR, WXY1);

        if (haveDown) {
            // shift (1,0): aligned vertical
#pragma unroll
            for (int k = 0; k < 4; k++)
                acc += shift_term(ca[k], cb[k], cc[k],
                                  na[k], nb[k], nc[k],
                                  cy[k], ny[k], WXY1);
            // shift (1,1): down-right
#pragma unroll
            for (int k = 0; k < 3; k++)
                acc += shift_term(ca[k], cb[k], cc[k],
                                  na[k+1], nb[k+1], nc[k+1],
                                  cy[k], ny[k+1], WXY2);
            if (hasR)
                acc += shift_term(ca[3], cb[3], cc[3], naR, nbR, ncR,
                                  cy[3], nyR, WXY2);
            // shift (1,-1): down-left
#pragma unroll
            for (int k = 1; k < 4; k++)
                acc += shift_term(ca[k], cb[k], cc[k],
                                  na[k-1], nb[k-1], nc[k-1],
                                  cy[k], ny[k-1], WXY2);
            if (hasL)
                acc += shift_term(ca[0], cb[0], cc[0], naL, nbL, ncL,
                                  cy[0], nyL, WXY2);
        }

        // ---- roll next -> current ----
#pragma unroll
        for (int k = 0; k < 4; k++) { cy[k]=ny[k]; ca[k]=na[k]; cb[k]=nb[k]; cc[k]=nc[k]; }
        cyR = nyR; caR = naR; cbR = nbR; ccR = ncR;
    }

    // ---- block reduction ----
#pragma unroll
    for (int o = 16; o > 0; o >>= 1)
        acc += __shfl_down_sync(FULL, acc, o);

    __shared__ float sm[4];
    const int wid = tid >> 5;
    if (lane == 0) sm[wid] = acc;
    __syncthreads();
    if (tid == 0) {
        float v = sm[0] + sm[1] + sm[2] + sm[3];
        const float SCALE = 1.0f / (float)((size_t)HH * WW * BB * 4);  // WEIGHT=1
        atomicAdd(out, v * SCALE);
    }
}

__global__ void zero_out_kernel(float* out) {
    if (threadIdx.x == 0) out[0] = 0.0f;
}

extern "C" void kernel_launch(void* const* d_in, const int* in_sizes, int n_in,
                              void* d_out, int out_size) {
    const float* ypr  = (const float*)d_in[0];   // y_pr  (16,2,512,512)
    // d_in[1] = y_gt (unused)
    const float* img  = (const float*)d_in[2];   // image (16,3,512,512)
    const int*   icls = (const int*)d_in[3];     // image_class (16,)
    float* out = (float*)d_out;

    zero_out_kernel<<<1, 32>>>(out);
    dim3 grid(HH / RPB, BB);
    crf_loss_kernel<<<grid, 128>>>(ypr, img, icls, out);
}